// round 14
// baseline (speedup 1.0000x reference)
#include <cuda_runtime.h>
#include <cuda_fp16.h>
#include <cstdint>

typedef unsigned long long ull;

#define Bt   4
#define St   1024
#define HIDt 1024
#define NHt  16
#define HDt  64
#define LOG2E 1.4426950408889634f
#define NELEM (Bt * NHt * St * HDt)
#define XN (Bt * St * HIDt)
#define WN (HIDt * HIDt)

// fp16 hi/lo split scratch. Q pre-scaled by 0.125. V stored single-fp16.
__device__ __half g_qh[NELEM], g_ql[NELEM];
__device__ __half g_kh[NELEM], g_kl[NELEM];
__device__ __half g_vh[NELEM];
__device__ __half g_xh[XN], g_xl[XN];
__device__ __half g_wh[3 * WN], g_wl[3 * WN];

// ---------------- helpers ----------------
__device__ __forceinline__ uint32_t cvta_s(const void* p) {
    return (uint32_t)__cvta_generic_to_shared(p);
}
__device__ __forceinline__ void ldsm4(uint32_t* r, uint32_t a) {
    asm volatile("ldmatrix.sync.aligned.m8n8.x4.shared.b16 {%0,%1,%2,%3},[%4];"
        : "=r"(r[0]), "=r"(r[1]), "=r"(r[2]), "=r"(r[3]) : "r"(a));
}
__device__ __forceinline__ void ldsm4t(uint32_t* r, uint32_t a) {
    asm volatile("ldmatrix.sync.aligned.m8n8.x4.trans.shared.b16 {%0,%1,%2,%3},[%4];"
        : "=r"(r[0]), "=r"(r[1]), "=r"(r[2]), "=r"(r[3]) : "r"(a));
}
__device__ __forceinline__ void mma_hf(float* c, const uint32_t* a, const uint32_t* b) {
    asm volatile("mma.sync.aligned.m16n8k16.row.col.f32.f16.f16.f32 "
        "{%0,%1,%2,%3},{%4,%5,%6,%7},{%8,%9},{%0,%1,%2,%3};"
        : "+f"(c[0]), "+f"(c[1]), "+f"(c[2]), "+f"(c[3])
        : "r"(a[0]), "r"(a[1]), "r"(a[2]), "r"(a[3]), "r"(b[0]), "r"(b[1]));
}
__device__ __forceinline__ uint32_t phf2(float e0, float e1) {
    uint32_t r; asm("cvt.rn.f16x2.f32 %0, %1, %2;" : "=r"(r) : "f"(e1), "f"(e0)); return r;
}
__device__ __forceinline__ void splith(float x, float& h, float& l) {
    h = __half2float(__float2half(x));
    l = x - h;
}
__device__ __forceinline__ float ex2(float x) {
    float y; asm("ex2.approx.ftz.f32 %0, %1;" : "=f"(y) : "f"(x)); return y;
}
__device__ __forceinline__ void cpa16(uint32_t dst, const void* src) {
    asm volatile("cp.async.cg.shared.global [%0], [%1], 16;" :: "r"(dst), "l"(src));
}
__device__ __forceinline__ void cpa4(uint32_t dst, const void* src) {
    asm volatile("cp.async.ca.shared.global [%0], [%1], 4;" :: "r"(dst), "l"(src));
}
__device__ __forceinline__ void cp_commit() { asm volatile("cp.async.commit_group;"); }
template<int N> __device__ __forceinline__ void cp_wait() {
    asm volatile("cp.async.wait_group %0;" :: "n"(N));
}

// ================= prep: split X / Wq / Wk / Wv to fp16 hi/lo ==============
__global__ __launch_bounds__(256)
void split_prep(const float* __restrict__ X,
                const float* __restrict__ Wq,
                const float* __restrict__ Wk,
                const float* __restrict__ Wv)
{
    const size_t idx = ((size_t)blockIdx.x * 256 + threadIdx.x) * 4;
    const float* src;
    __half *dh, *dl;
    size_t off;
    if (idx < XN)               { src = X;  dh = g_xh; dl = g_xl; off = idx; }
    else if (idx < XN + WN)     { src = Wq; dh = g_wh; dl = g_wl; off = idx - XN; }
    else if (idx < XN + 2 * WN) { src = Wk; dh = g_wh + WN; dl = g_wl + WN; off = idx - XN - WN; }
    else                        { src = Wv; dh = g_wh + 2 * WN; dl = g_wl + 2 * WN; off = idx - XN - 2 * WN; }
    const float4 v = *(const float4*)(src + off);
    float h0, l0, h1, l1, h2, l2, h3, l3;
    splith(v.x, h0, l0); splith(v.y, h1, l1);
    splith(v.z, h2, l2); splith(v.w, h3, l3);
    *(uint2*)(dh + off) = make_uint2(phf2(h0, h1), phf2(h2, h3));
    *(uint2*)(dl + off) = make_uint2(phf2(l0, l1), phf2(l2, l3));
}

// ===== Fused projection kernel: z=0 -> QK (128x256, 3-term), z=1 -> V ======
#define QK_S_AH 0
#define QK_S_AL 24576
#define QK_S_BH 49152
#define QK_S_BL 98304
#define QK2_SMEM 147456

__global__ __launch_bounds__(512, 1)
void qkv_fused(const float* __restrict__ bq, const float* __restrict__ bk,
               const float* __restrict__ bv)
{
    extern __shared__ __align__(16) char smq[];
    const uint32_t sb = cvta_s(smq);

    const int tid = threadIdx.x;
    const int wid = tid >> 5, lane = tid & 31;
    const int bx = blockIdx.x, by = blockIdx.y;
    const int chalf = lane >> 4;

    if (blockIdx.z == 0) {
        const int wm = (wid & 3) * 32;
        const int wn = (wid >> 2) * 64;

        const int rA = tid >> 2, cA = tid & 3;
        const __half* Axh = g_xh + (size_t)(by * 128 + rA) * HIDt;
        const __half* Axl = g_xl + (size_t)(by * 128 + rA) * HIDt;
        const uint32_t swA = (uint32_t)rA * 64 + (((uint32_t)cA ^ ((rA >> 1) & 3)) << 4);

        const int rB = tid >> 1, chp = (tid & 1) * 2;
        const size_t woff = (size_t)(rB >> 7) * WN + (size_t)(bx * 128 + (rB & 127)) * HIDt;
        const __half* Bwh = g_wh + woff;
        const __half* Bwl = g_wl + woff;
        const uint32_t xsB = (rB >> 1) & 3;
        const uint32_t swB0 = (uint32_t)rB * 64 + ((((uint32_t)chp + 0) ^ xsB) << 4);
        const uint32_t swB1 = (uint32_t)rB * 64 + ((((uint32_t)chp + 1) ^ xsB) << 4);

#define QKISSUE(slab, st) do {                                                  \
        const int k0_ = (slab) * 32;                                            \
        cpa16(sb + QK_S_AH + (st) * 8192 + swA, Axh + k0_ + cA * 8);            \
        cpa16(sb + QK_S_AL + (st) * 8192 + swA, Axl + k0_ + cA * 8);            \
        cpa16(sb + QK_S_BH + (st) * 16384 + swB0, Bwh + k0_ + chp * 8);         \
        cpa16(sb + QK_S_BH + (st) * 16384 + swB1, Bwh + k0_ + chp * 8 + 8);     \
        cpa16(sb + QK_S_BL + (st) * 16384 + swB0, Bwl + k0_ + chp * 8);         \
        cpa16(sb + QK_S_BL + (st) * 16384 + swB1, Bwl + k0_ + chp * 8 + 8);     \
        cp_commit();                                                            \
    } while (0)

        float acc[2][8][4];
#pragma unroll
        for (int i = 0; i < 2; ++i)
#pragma unroll
            for (int j = 0; j < 8; ++j)
#pragma unroll
                for (int k = 0; k < 4; ++k) acc[i][j][k] = 0.f;

        uint32_t abase_r[2], xa[2];
#pragma unroll
        for (int mi = 0; mi < 2; ++mi) {
            const int arow = wm + mi * 16 + (lane & 15);
            abase_r[mi] = (uint32_t)arow * 64;
            xa[mi] = (arow >> 1) & 3;
        }
        uint32_t bbase_r[4], xb[4];
#pragma unroll
        for (int nb = 0; nb < 4; ++nb) {
            const int brow = wn + nb * 16 + (lane & 15);
            bbase_r[nb] = (uint32_t)brow * 64;
            xb[nb] = (brow >> 1) & 3;
        }

        QKISSUE(0, 0);
        QKISSUE(1, 1);

        for (int s = 0; s < 32; ++s) {
            const int st = s % 3;
            if (s < 31) cp_wait<1>(); else cp_wait<0>();
            __syncthreads();
            if (s + 2 < 32) QKISSUE(s + 2, (s + 2) % 3);

            const uint32_t ah = sb + QK_S_AH + st * 8192;
            const uint32_t al = sb + QK_S_AL + st * 8192;
            const uint32_t bh = sb + QK_S_BH + st * 16384;
            const uint32_t bl = sb + QK_S_BL + st * 16384;
#pragma unroll
            for (int kb = 0; kb < 2; ++kb) {
                const uint32_t ccol = kb * 2 + chalf;
                uint32_t a_h[2][4], a_l[2][4];
#pragma unroll
                for (int mi = 0; mi < 2; ++mi) {
                    const uint32_t aoff = abase_r[mi] + ((ccol ^ xa[mi]) << 4);
                    ldsm4(a_h[mi], ah + aoff);
                    ldsm4(a_l[mi], al + aoff);
                }
#pragma unroll
                for (int nb = 0; nb < 4; ++nb) {
                    const uint32_t boff = bbase_r[nb] + ((ccol ^ xb[nb]) << 4);
                    uint32_t bh4[4], bl4[4];
                    ldsm4(bh4, bh + boff);
                    ldsm4(bl4, bl + boff);
                    uint32_t b0h[2] = {bh4[0], bh4[2]}, b1h[2] = {bh4[1], bh4[3]};
                    uint32_t b0l[2] = {bl4[0], bl4[2]}, b1l[2] = {bl4[1], bl4[3]};
#pragma unroll
                    for (int mi = 0; mi < 2; ++mi) {
                        float* c0 = acc[mi][nb * 2];
                        float* c1 = acc[mi][nb * 2 + 1];
                        mma_hf(c0, a_h[mi], b0h); mma_hf(c0, a_l[mi], b0h); mma_hf(c0, a_h[mi], b0l);
                        mma_hf(c1, a_h[mi], b1h); mma_hf(c1, a_l[mi], b1h); mma_hf(c1, a_h[mi], b1l);
                    }
                }
            }
        }
        __syncthreads();

        uint32_t* Cp = (uint32_t*)smq;
        const float* bias = (wn < 128) ? bq : bk;
        const float qs = (wn < 128) ? 0.125f : 1.0f;
#pragma unroll
        for (int mi = 0; mi < 2; ++mi) {
#pragma unroll
            for (int nb2 = 0; nb2 < 8; ++nb2) {
                const int ncol = wn + nb2 * 8 + (lane & 3) * 2;
                const float2 bv2 = *(const float2*)(bias + bx * 128 + (ncol & 127));
                const int colu = ncol >> 1;
#pragma unroll
                for (int rr = 0; rr < 2; ++rr) {
                    const int row = wm + mi * 16 + (lane >> 2) + rr * 8;
                    const float x0 = (acc[mi][nb2][rr * 2 + 0] + bv2.x) * qs;
                    const float x1 = (acc[mi][nb2][rr * 2 + 1] + bv2.y) * qs;
                    float h0, l0, h1, l1;
                    splith(x0, h0, l0); splith(x1, h1, l1);
                    Cp[row * 132 + colu]         = phf2(h0, h1);
                    Cp[16896 + row * 132 + colu] = phf2(l0, l1);
                }
            }
        }
        __syncthreads();

#pragma unroll
        for (int it = 0; it < 16; ++it) {
            const int idx = tid + it * 512;
            const int a = idx >> 12;
            const int rem = idx & 4095;
            const int row = rem >> 5;
            const int j = rem & 31;
            const uint32_t sbyte = (uint32_t)a * 67584 + (uint32_t)row * 528 + j * 16;
            const uint4 v = *(const uint4*)(smq + sbyte);
            const int n = j * 8;
            const int ncol = n & 127;
            __half* dst = (n < 128) ? (a ? g_ql : g_qh) : (a ? g_kl : g_kh);
            const int m = by * 128 + row;
            const int bsel = m >> 10, sq = m & 1023;
            const int head = bx * 2 + (ncol >> 6);
            const size_t off = (((size_t)(bsel * NHt + head)) * St + sq) * HDt + (ncol & 63);
            *(uint4*)(dst + off) = v;
        }
#undef QKISSUE
    } else {
        // ---------------- V path: 128x128, 1-term, 512 threads, 4x4 warps --
        const int wm = (wid & 3) * 32;
        const int wn4 = (wid >> 2) * 32;

        const int rA = tid >> 2, cA = tid & 3;
        const __half* Axh = g_xh + (size_t)(by * 128 + rA) * HIDt + cA * 8;
        const __half* Bwh = g_wh + 2 * (size_t)WN + (size_t)(bx * 128 + rA) * HIDt + cA * 8;
        const uint32_t swA = (uint32_t)rA * 64 + (((uint32_t)cA ^ ((rA >> 1) & 3)) << 4);

#define VISSUE(slab, st) do {                                            \
        const int k0_ = (slab) * 32;                                     \
        cpa16(sb + (st) * 8192 + swA, Axh + k0_);                        \
        cpa16(sb + 24576 + (st) * 8192 + swA, Bwh + k0_);                \
        cp_commit();                                                     \
    } while (0)

        float acc[2][4][4];
#pragma unroll
        for (int i = 0; i < 2; ++i)
#pragma unroll
            for (int j = 0; j < 4; ++j)
#pragma unroll
                for (int k = 0; k < 4; ++k) acc[i][j][k] = 0.f;

        uint32_t abase_r[2], xa[2];
#pragma unroll
        for (int mi = 0; mi < 2; ++mi) {
            const int arow = wm + mi * 16 + (lane & 15);
            abase_r[mi] = (uint32_t)arow * 64;
            xa[mi] = (arow >> 1) & 3;
        }
        uint32_t bbase_r[2], xb[2];
#pragma unroll
        for (int nb = 0; nb < 2; ++nb) {
            const int brow = wn4 + nb * 16 + (lane & 15);
            bbase_r[nb] = (uint32_t)brow * 64;
            xb[nb] = (brow >> 1) & 3;
        }

        VISSUE(0, 0);
        VISSUE(1, 1);

        for (int s = 0; s < 32; ++s) {
            const int st = s % 3;
            if (s < 31) cp_wait<1>(); else cp_wait<0>();
            __syncthreads();
            if (s + 2 < 32) VISSUE(s + 2, (s + 2) % 3);

            const uint32_t ah = sb + st * 8192;
            const uint32_t bh = sb + 24576 + st * 8192;
#pragma unroll
            for (int kb = 0; kb < 2; ++kb) {
                const uint32_t ccol = kb * 2 + chalf;
                uint32_t a_h[2][4];
#pragma unroll
                for (int mi = 0; mi < 2; ++mi) {
                    const uint32_t aoff = abase_r[mi] + ((ccol ^ xa[mi]) << 4);
                    ldsm4(a_h[mi], ah + aoff);
                }
#pragma unroll
                for (int nb = 0; nb < 2; ++nb) {
                    const uint32_t boff = bbase_r[nb] + ((ccol ^ xb[nb]) << 4);
                    uint32_t bh4[4];
                    ldsm4(bh4, bh + boff);
                    uint32_t b0h[2] = {bh4[0], bh4[2]}, b1h[2] = {bh4[1], bh4[3]};
#pragma unroll
                    for (int mi = 0; mi < 2; ++mi) {
                        mma_hf(acc[mi][nb * 2],     a_h[mi], b0h);
                        mma_hf(acc[mi][nb * 2 + 1], a_h[mi], b1h);
                    }
                }
            }
        }
        __syncthreads();

        uint32_t* Ch = (uint32_t*)smq;
#pragma unroll
        for (int mi = 0; mi < 2; ++mi) {
#pragma unroll
            for (int n8 = 0; n8 < 4; ++n8) {
                const int ncol = wn4 + n8 * 8 + (lane & 3) * 2;
                const float2 bv2 = *(const float2*)(bv + bx * 128 + ncol);
                const int colu = ncol >> 1;
#pragma unroll
                for (int rr = 0; rr < 2; ++rr) {
                    const int row = wm + mi * 16 + (lane >> 2) + rr * 8;
                    const float x0 = acc[mi][n8][rr * 2 + 0] + bv2.x;
                    const float x1 = acc[mi][n8][rr * 2 + 1] + bv2.y;
                    Ch[row * 68 + colu] = phf2(x0, x1);
                }
            }
        }
        __syncthreads();

#pragma unroll
        for (int it = 0; it < 4; ++it) {
            const int idx = tid + it * 512;
            const int j = idx & 7;
            const int row = (idx >> 3) & 127;
            const int half = (idx >> 10) & 1;
            const uint32_t sbyte = (uint32_t)row * 272 + half * 128 + j * 16;
            const uint4 v = *(const uint4*)(smq + sbyte);
            const int m = by * 128 + row;
            const int bsel = m >> 10, sq = m & 1023;
            const int head = bx * 2 + half;
            const size_t off = (((size_t)(bsel * NHt + head)) * St + sq) * HDt + j * 8;
            *(uint4*)(g_vh + off) = v;
        }
#undef VISSUE
    }
}

// ====== Flash attention: 64-q CTA, 128 thr, 2-stage KV, Q frags hoisted ====
#define A_STAGE 27648
#define A_KV0   18432
#define A_MB    73728
#define ASMEM   74240

__global__ __launch_bounds__(128)
void attn_mma(const float* __restrict__ mask, float* __restrict__ out)
{
    extern __shared__ __align__(16) char sma[];
    const uint32_t sb = cvta_s(sma);
    __half (*Qh)[72] = (__half(*)[72])(sma);
    __half (*Ql)[72] = (__half(*)[72])(sma + 9216);

    const int tid = threadIdx.x;
    const int lane = tid & 31, wid = tid >> 5;
    const int qt = blockIdx.x, h = blockIdx.y, b = blockIdx.z;

    const size_t bh = ((size_t)(b * NHt + h)) * St * HDt;
    const __half* qhp = g_qh + bh + (size_t)qt * 64 * HDt;
    const __half* qlp = g_ql + bh + (size_t)qt * 64 * HDt;
    const __half* khp = g_kh + bh;
    const __half* klp = g_kl + bh;
    const __half* vhp = g_vh + bh;
    const float* mrow = mask + (size_t)b * St;

#define AISSUE(ktv, stv) do {                                                 \
        const size_t ko_ = (size_t)(ktv) * 64 * HDt;                          \
        const uint32_t base_ = sb + A_KV0 + (stv) * A_STAGE;                  \
        _Pragma("unroll")                                                     \
        for (int j_ = 0; j_ < 4; ++j_) {                                      \
            const int i_ = tid + j_ * 128;                                    \
            const int r_ = i_ >> 3, c_ = (i_ & 7) * 8;                        \
            const uint32_t d_ = base_ + (uint32_t)r_ * 144 + c_ * 2;          \
            cpa16(d_,         khp + ko_ + r_ * 64 + c_);                      \
            cpa16(d_ + 9216,  klp + ko_ + r_ * 64 + c_);                      \
            cpa16(d_ + 18432, vhp + ko_ + r_ * 64 + c_);                      \
        }                                                                     \
        if (tid < 64) cpa4(sb + A_MB + (stv) * 256 + tid * 4,                 \
                           mrow + (ktv) * 64 + tid);                          \
        cp_commit();                                                          \
    } while (0)

    // stage Q to smem, then hoist all Q fragments into registers (loop-invariant)
    for (int i = tid; i < 512; i += 128) {
        const int r = i >> 3, c = (i & 7) * 8;
        *(uint4*)&Qh[r][c] = *(const uint4*)(qhp + r * 64 + c);
        *(uint4*)&Ql[r][c] = *(const uint4*)(qlp + r * 64 + c);
    }

    AISSUE(0, 0);
    __syncthreads();   // Q stores visible to all warps before ldsm

    uint32_t qf_h[4][4], qf_l[4][4];
    {
        const int qrow = wid * 16 + (lane & 15);
#pragma unroll
        for (int kb = 0; kb < 4; ++kb) {
            const int qcol = kb * 16 + (lane >> 4) * 8;
            ldsm4(qf_h[kb], cvta_s(&Qh[qrow][qcol]));
            ldsm4(qf_l[kb], cvta_s(&Ql[qrow][qcol]));
        }
    }

    float o[8][4];
#pragma unroll
    for (int j = 0; j < 8; ++j)
#pragma unroll
        for (int k = 0; k < 4; ++k) o[j][k] = 0.f;
    float m0 = -1e30f, m1 = -1e30f, l0 = 0.f, l1 = 0.f;

    for (int kt = 0; kt < 16; ++kt) {
        const int st = kt & 1;
        cp_wait<0>();
        __syncthreads();
        if (kt + 1 < 16) AISSUE(kt + 1, st ^ 1);

        const uint32_t kh = sb + A_KV0 + st * A_STAGE;
        const uint32_t kl = kh + 9216;
        const uint32_t vs = kh + 18432;
        const float* mbs = (const float*)(sma + A_MB + st * 256);

        float s[8][4];
#pragma unroll
        for (int j = 0; j < 8; ++j)
#pragma unroll
            for (int k = 0; k < 4; ++k) s[j][k] = 0.f;

#pragma unroll
        for (int kb = 0; kb < 4; ++kb) {
            const int qcol = kb * 16 + (lane >> 4) * 8;
#pragma unroll
            for (int nb = 0; nb < 4; ++nb) {
                const int krow = nb * 16 + (lane & 15);
                const uint32_t koff = (uint32_t)krow * 144 + qcol * 2;
                uint32_t bh4[4], bl4[4];
                ldsm4(bh4, kh + koff);
                ldsm4(bl4, kl + koff);
                uint32_t b0h[2] = {bh4[0], bh4[2]}, b1h[2] = {bh4[1], bh4[3]};
                uint32_t b0l[2] = {bl4[0], bl4[2]}, b1l[2] = {bl4[1], bl4[3]};
                float* s0 = s[nb * 2];
                float* s1 = s[nb * 2 + 1];
                mma_hf(s0, qf_h[kb], b0h); mma_hf(s0, qf_l[kb], b0h); mma_hf(s0, qf_h[kb], b0l);
                mma_hf(s1, qf_h[kb], b1h); mma_hf(s1, qf_l[kb], b1h); mma_hf(s1, qf_h[kb], b1l);
            }
        }

        float rmax0 = -1e30f, rmax1 = -1e30f;
#pragma unroll
        for (int j = 0; j < 8; ++j) {
            const float bm0 = (mbs[j * 8 + (lane & 3) * 2]     - 2.0f) * 1.0e6f;
            const float bm1 = (mbs[j * 8 + (lane & 3) * 2 + 1] - 2.0f) * 1.0e6f;
            s[j][0] += bm0; s[j][1] += bm1; s[j][2] += bm0; s[j][3] += bm1;
            rmax0 = fmaxf(rmax0, fmaxf(s[j][0], s[j][1]));
            rmax1 = fmaxf(rmax1, fmaxf(s[j][2], s[j][3]));
        }
        rmax0 = fmaxf(rmax0, __shfl_xor_sync(0xffffffffu, rmax0, 1));
        rmax0 = fmaxf(rmax0, __shfl_xor_sync(0xffffffffu, rmax0, 2));
        rmax1 = fmaxf(rmax1, __shfl_xor_sync(0xffffffffu, rmax1, 1));
        rmax1 = fmaxf(rmax1, __shfl_xor_sync(0xffffffffu, rmax1, 2));
        const float mn0 = fmaxf(m0, rmax0), mn1 = fmaxf(m1, rmax1);
        const float c0 = ex2((m0 - mn0) * LOG2E), c1 = ex2((m1 - mn1) * LOG2E);
        float rs0 = 0.f, rs1 = 0.f;

        uint32_t pa[4][4];
#pragma unroll
        for (int j2 = 0; j2 < 4; ++j2) {
#pragma unroll
            for (int q = 0; q < 2; ++q) {
                const int j = j2 * 2 + q;
                const float p0 = ex2((s[j][0] - mn0) * LOG2E);
                const float p1 = ex2((s[j][1] - mn0) * LOG2E);
                const float p2 = ex2((s[j][2] - mn1) * LOG2E);
                const float p3 = ex2((s[j][3] - mn1) * LOG2E);
                rs0 += p0 + p1; rs1 += p2 + p3;
                pa[j2][q * 2 + 0] = phf2(p0, p1);
                pa[j2][q * 2 + 1] = phf2(p2, p3);
            }
        }

        rs0 += __shfl_xor_sync(0xffffffffu, rs0, 1);
        rs0 += __shfl_xor_sync(0xffffffffu, rs0, 2);
        rs1 += __shfl_xor_sync(0xffffffffu, rs1, 1);
        rs1 += __shfl_xor_sync(0xffffffffu, rs1, 2);
        l0 = l0 * c0 + rs0; l1 = l1 * c1 + rs1;
        m0 = mn0; m1 = mn1;
#pragma unroll
        for (int j = 0; j < 8; ++j) {
            o[j][0] *= c0; o[j][1] *= c0; o[j][2] *= c1; o[j][3] *= c1;
        }

        const int grp = lane >> 3, li = lane & 7;
#pragma unroll
        for (int j2 = 0; j2 < 4; ++j2) {
            const int vr = j2 * 16 + ((grp & 1) ? 8 : 0) + li;
#pragma unroll
            for (int db = 0; db < 4; ++db) {
                const int vc = db * 16 + ((grp >= 2) ? 8 : 0);
                uint32_t vh4[4];
                ldsm4t(vh4, vs + (uint32_t)vr * 144 + vc * 2);
                uint32_t b0h[2] = {vh4[0], vh4[1]}, b1h[2] = {vh4[2], vh4[3]};
                mma_hf(o[db * 2],     pa[j2], b0h);
                mma_hf(o[db * 2 + 1], pa[j2], b1h);
            }
        }
    }

    const float inv0 = 1.f / l0, inv1 = 1.f / l1;
    const int r0 = qt * 64 + wid * 16 + (lane >> 2);
#pragma unroll
    for (int db2 = 0; db2 < 8; ++db2) {
        const int d = db2 * 8 + (lane & 3) * 2;
        float2 v0 = make_float2(o[db2][0] * inv0, o[db2][1] * inv0);
        float2 v1 = make_float2(o[db2][2] * inv1, o[db2][3] * inv1);
        *(float2*)(out + (size_t)(b * St + r0) * HIDt + h * 64 + d) = v0;
        *(float2*)(out + (size_t)(b * St + r0 + 8) * HIDt + h * 64 + d) = v1;
    }
#undef AISSUE
}

extern "C" void kernel_launch(void* const* d_in, const int* in_sizes, int n_in,
                              void* d_out, int out_size)
{
    const float* X    = (const float*)d_in[0];
    const float* mask = (const float*)d_in[1];
    const float* Wq   = (const float*)d_in[2];
    const float* bq   = (const float*)d_in[3];
    const float* Wk   = (const float*)d_in[4];
    const float* bk   = (const float*)d_in[5];
    const float* Wv   = (const float*)d_in[6];
    const float* bv   = (const float*)d_in[7];
    float* out = (float*)d_out;

    cudaFuncSetAttribute(qkv_fused, cudaFuncAttributeMaxDynamicSharedMemorySize, QK2_SMEM);
    cudaFuncSetAttribute(attn_mma, cudaFuncAttributeMaxDynamicSharedMemorySize, ASMEM);

    const int total4 = (XN + 3 * WN) / 4;
    split_prep<<<total4 / 256, 256>>>(X, Wq, Wk, Wv);

    dim3 gqkv(HIDt / 128, (Bt * St) / 128, 2);
    qkv_fused<<<gqkv, 512, QK2_SMEM>>>(bq, bk, bv);

    dim3 g2(St / 64, NHt, Bt);
    attn_mma<<<g2, 128, ASMEM>>>(mask, out);
}

// round 15
// speedup vs baseline: 1.0131x; 1.0131x over previous
#include <cuda_runtime.h>
#include <cuda_fp16.h>
#include <cstdint>

typedef unsigned long long ull;

#define Bt   4
#define St   1024
#define HIDt 1024
#define NHt  16
#define HDt  64
#define LOG2E 1.4426950408889634f
#define NELEM (Bt * NHt * St * HDt)
#define XN (Bt * St * HIDt)
#define WN (HIDt * HIDt)

// fp16 hi/lo split scratch. Q pre-scaled by 0.125. V stored single-fp16.
__device__ __half g_qh[NELEM], g_ql[NELEM];
__device__ __half g_kh[NELEM], g_kl[NELEM];
__device__ __half g_vh[NELEM];
__device__ __half g_xh[XN], g_xl[XN];
__device__ __half g_wh[3 * WN], g_wl[3 * WN];

// ---------------- helpers ----------------
__device__ __forceinline__ uint32_t cvta_s(const void* p) {
    return (uint32_t)__cvta_generic_to_shared(p);
}
__device__ __forceinline__ void ldsm4(uint32_t* r, uint32_t a) {
    asm volatile("ldmatrix.sync.aligned.m8n8.x4.shared.b16 {%0,%1,%2,%3},[%4];"
        : "=r"(r[0]), "=r"(r[1]), "=r"(r[2]), "=r"(r[3]) : "r"(a));
}
__device__ __forceinline__ void ldsm4t(uint32_t* r, uint32_t a) {
    asm volatile("ldmatrix.sync.aligned.m8n8.x4.trans.shared.b16 {%0,%1,%2,%3},[%4];"
        : "=r"(r[0]), "=r"(r[1]), "=r"(r[2]), "=r"(r[3]) : "r"(a));
}
__device__ __forceinline__ void mma_hf(float* c, const uint32_t* a, const uint32_t* b) {
    asm volatile("mma.sync.aligned.m16n8k16.row.col.f32.f16.f16.f32 "
        "{%0,%1,%2,%3},{%4,%5,%6,%7},{%8,%9},{%0,%1,%2,%3};"
        : "+f"(c[0]), "+f"(c[1]), "+f"(c[2]), "+f"(c[3])
        : "r"(a[0]), "r"(a[1]), "r"(a[2]), "r"(a[3]), "r"(b[0]), "r"(b[1]));
}
__device__ __forceinline__ uint32_t phf2(float e0, float e1) {
    uint32_t r; asm("cvt.rn.f16x2.f32 %0, %1, %2;" : "=r"(r) : "f"(e1), "f"(e0)); return r;
}
__device__ __forceinline__ void splith(float x, float& h, float& l) {
    h = __half2float(__float2half(x));
    l = x - h;
}
__device__ __forceinline__ float ex2(float x) {
    float y; asm("ex2.approx.ftz.f32 %0, %1;" : "=f"(y) : "f"(x)); return y;
}
__device__ __forceinline__ void cpa16(uint32_t dst, const void* src) {
    asm volatile("cp.async.cg.shared.global [%0], [%1], 16;" :: "r"(dst), "l"(src));
}
__device__ __forceinline__ void cpa4(uint32_t dst, const void* src) {
    asm volatile("cp.async.ca.shared.global [%0], [%1], 4;" :: "r"(dst), "l"(src));
}
__device__ __forceinline__ void cp_commit() { asm volatile("cp.async.commit_group;"); }
template<int N> __device__ __forceinline__ void cp_wait() {
    asm volatile("cp.async.wait_group %0;" :: "n"(N));
}

// ================= prep: split X / Wq / Wk / Wv to fp16 hi/lo ==============
__global__ __launch_bounds__(256)
void split_prep(const float* __restrict__ X,
                const float* __restrict__ Wq,
                const float* __restrict__ Wk,
                const float* __restrict__ Wv)
{
    const size_t idx = ((size_t)blockIdx.x * 256 + threadIdx.x) * 4;
    const float* src;
    __half *dh, *dl;
    size_t off;
    if (idx < XN)               { src = X;  dh = g_xh; dl = g_xl; off = idx; }
    else if (idx < XN + WN)     { src = Wq; dh = g_wh; dl = g_wl; off = idx - XN; }
    else if (idx < XN + 2 * WN) { src = Wk; dh = g_wh + WN; dl = g_wl + WN; off = idx - XN - WN; }
    else                        { src = Wv; dh = g_wh + 2 * WN; dl = g_wl + 2 * WN; off = idx - XN - 2 * WN; }
    const float4 v = *(const float4*)(src + off);
    float h0, l0, h1, l1, h2, l2, h3, l3;
    splith(v.x, h0, l0); splith(v.y, h1, l1);
    splith(v.z, h2, l2); splith(v.w, h3, l3);
    *(uint2*)(dh + off) = make_uint2(phf2(h0, h1), phf2(h2, h3));
    *(uint2*)(dl + off) = make_uint2(phf2(l0, l1), phf2(l2, l3));
}

// ===== Fused projection kernel: z=0 -> QK (128x256, 3-term), z=1 -> V ======
#define QK_S_AH 0
#define QK_S_AL 24576
#define QK_S_BH 49152
#define QK_S_BL 98304
#define QK2_SMEM 147456

__global__ __launch_bounds__(512, 1)
void qkv_fused(const float* __restrict__ bq, const float* __restrict__ bk,
               const float* __restrict__ bv)
{
    extern __shared__ __align__(16) char smq[];
    const uint32_t sb = cvta_s(smq);

    const int tid = threadIdx.x;
    const int wid = tid >> 5, lane = tid & 31;
    const int bx = blockIdx.x, by = blockIdx.y;
    const int chalf = lane >> 4;

    if (blockIdx.z == 0) {
        const int wm = (wid & 3) * 32;
        const int wn = (wid >> 2) * 64;

        const int rA = tid >> 2, cA = tid & 3;
        const __half* Axh = g_xh + (size_t)(by * 128 + rA) * HIDt;
        const __half* Axl = g_xl + (size_t)(by * 128 + rA) * HIDt;
        const uint32_t swA = (uint32_t)rA * 64 + (((uint32_t)cA ^ ((rA >> 1) & 3)) << 4);

        const int rB = tid >> 1, chp = (tid & 1) * 2;
        const size_t woff = (size_t)(rB >> 7) * WN + (size_t)(bx * 128 + (rB & 127)) * HIDt;
        const __half* Bwh = g_wh + woff;
        const __half* Bwl = g_wl + woff;
        const uint32_t xsB = (rB >> 1) & 3;
        const uint32_t swB0 = (uint32_t)rB * 64 + ((((uint32_t)chp + 0) ^ xsB) << 4);
        const uint32_t swB1 = (uint32_t)rB * 64 + ((((uint32_t)chp + 1) ^ xsB) << 4);

#define QKISSUE(slab, st) do {                                                  \
        const int k0_ = (slab) * 32;                                            \
        cpa16(sb + QK_S_AH + (st) * 8192 + swA, Axh + k0_ + cA * 8);            \
        cpa16(sb + QK_S_AL + (st) * 8192 + swA, Axl + k0_ + cA * 8);            \
        cpa16(sb + QK_S_BH + (st) * 16384 + swB0, Bwh + k0_ + chp * 8);         \
        cpa16(sb + QK_S_BH + (st) * 16384 + swB1, Bwh + k0_ + chp * 8 + 8);     \
        cpa16(sb + QK_S_BL + (st) * 16384 + swB0, Bwl + k0_ + chp * 8);         \
        cpa16(sb + QK_S_BL + (st) * 16384 + swB1, Bwl + k0_ + chp * 8 + 8);     \
        cp_commit();                                                            \
    } while (0)

        float acc[2][8][4];
#pragma unroll
        for (int i = 0; i < 2; ++i)
#pragma unroll
            for (int j = 0; j < 8; ++j)
#pragma unroll
                for (int k = 0; k < 4; ++k) acc[i][j][k] = 0.f;

        uint32_t abase_r[2], xa[2];
#pragma unroll
        for (int mi = 0; mi < 2; ++mi) {
            const int arow = wm + mi * 16 + (lane & 15);
            abase_r[mi] = (uint32_t)arow * 64;
            xa[mi] = (arow >> 1) & 3;
        }
        uint32_t bbase_r[4], xb[4];
#pragma unroll
        for (int nb = 0; nb < 4; ++nb) {
            const int brow = wn + nb * 16 + (lane & 15);
            bbase_r[nb] = (uint32_t)brow * 64;
            xb[nb] = (brow >> 1) & 3;
        }

        QKISSUE(0, 0);
        QKISSUE(1, 1);

        for (int s = 0; s < 32; ++s) {
            const int st = s % 3;
            if (s < 31) cp_wait<1>(); else cp_wait<0>();
            __syncthreads();
            if (s + 2 < 32) QKISSUE(s + 2, (s + 2) % 3);

            const uint32_t ah = sb + QK_S_AH + st * 8192;
            const uint32_t al = sb + QK_S_AL + st * 8192;
            const uint32_t bh = sb + QK_S_BH + st * 16384;
            const uint32_t bl = sb + QK_S_BL + st * 16384;
#pragma unroll
            for (int kb = 0; kb < 2; ++kb) {
                const uint32_t ccol = kb * 2 + chalf;
                uint32_t a_h[2][4], a_l[2][4];
#pragma unroll
                for (int mi = 0; mi < 2; ++mi) {
                    const uint32_t aoff = abase_r[mi] + ((ccol ^ xa[mi]) << 4);
                    ldsm4(a_h[mi], ah + aoff);
                    ldsm4(a_l[mi], al + aoff);
                }
#pragma unroll
                for (int nb = 0; nb < 4; ++nb) {
                    const uint32_t boff = bbase_r[nb] + ((ccol ^ xb[nb]) << 4);
                    uint32_t bh4[4], bl4[4];
                    ldsm4(bh4, bh + boff);
                    ldsm4(bl4, bl + boff);
                    uint32_t b0h[2] = {bh4[0], bh4[2]}, b1h[2] = {bh4[1], bh4[3]};
                    uint32_t b0l[2] = {bl4[0], bl4[2]}, b1l[2] = {bl4[1], bl4[3]};
#pragma unroll
                    for (int mi = 0; mi < 2; ++mi) {
                        float* c0 = acc[mi][nb * 2];
                        float* c1 = acc[mi][nb * 2 + 1];
                        // interleaved: per-accumulator order unchanged (h*h, l*h, h*l)
                        mma_hf(c0, a_h[mi], b0h); mma_hf(c1, a_h[mi], b1h);
                        mma_hf(c0, a_l[mi], b0h); mma_hf(c1, a_l[mi], b1h);
                        mma_hf(c0, a_h[mi], b0l); mma_hf(c1, a_h[mi], b1l);
                    }
                }
            }
        }
        __syncthreads();

        uint32_t* Cp = (uint32_t*)smq;
        const float* bias = (wn < 128) ? bq : bk;
        const float qs = (wn < 128) ? 0.125f : 1.0f;
#pragma unroll
        for (int mi = 0; mi < 2; ++mi) {
#pragma unroll
            for (int nb2 = 0; nb2 < 8; ++nb2) {
                const int ncol = wn + nb2 * 8 + (lane & 3) * 2;
                const float2 bv2 = *(const float2*)(bias + bx * 128 + (ncol & 127));
                const int colu = ncol >> 1;
#pragma unroll
                for (int rr = 0; rr < 2; ++rr) {
                    const int row = wm + mi * 16 + (lane >> 2) + rr * 8;
                    const float x0 = (acc[mi][nb2][rr * 2 + 0] + bv2.x) * qs;
                    const float x1 = (acc[mi][nb2][rr * 2 + 1] + bv2.y) * qs;
                    float h0, l0, h1, l1;
                    splith(x0, h0, l0); splith(x1, h1, l1);
                    Cp[row * 132 + colu]         = phf2(h0, h1);
                    Cp[16896 + row * 132 + colu] = phf2(l0, l1);
                }
            }
        }
        __syncthreads();

#pragma unroll
        for (int it = 0; it < 16; ++it) {
            const int idx = tid + it * 512;
            const int a = idx >> 12;
            const int rem = idx & 4095;
            const int row = rem >> 5;
            const int j = rem & 31;
            const uint32_t sbyte = (uint32_t)a * 67584 + (uint32_t)row * 528 + j * 16;
            const uint4 v = *(const uint4*)(smq + sbyte);
            const int n = j * 8;
            const int ncol = n & 127;
            __half* dst = (n < 128) ? (a ? g_ql : g_qh) : (a ? g_kl : g_kh);
            const int m = by * 128 + row;
            const int bsel = m >> 10, sq = m & 1023;
            const int head = bx * 2 + (ncol >> 6);
            const size_t off = (((size_t)(bsel * NHt + head)) * St + sq) * HDt + (ncol & 63);
            *(uint4*)(dst + off) = v;
        }
#undef QKISSUE
    } else {
        // ---------------- V path: 128x128, 1-term, 512 threads, 4x4 warps --
        const int wm = (wid & 3) * 32;
        const int wn4 = (wid >> 2) * 32;

        const int rA = tid >> 2, cA = tid & 3;
        const __half* Axh = g_xh + (size_t)(by * 128 + rA) * HIDt + cA * 8;
        const __half* Bwh = g_wh + 2 * (size_t)WN + (size_t)(bx * 128 + rA) * HIDt + cA * 8;
        const uint32_t swA = (uint32_t)rA * 64 + (((uint32_t)cA ^ ((rA >> 1) & 3)) << 4);

#define VISSUE(slab, st) do {                                            \
        const int k0_ = (slab) * 32;                                     \
        cpa16(sb + (st) * 8192 + swA, Axh + k0_);                        \
        cpa16(sb + 24576 + (st) * 8192 + swA, Bwh + k0_);                \
        cp_commit();                                                     \
    } while (0)

        float acc[2][4][4];
#pragma unroll
        for (int i = 0; i < 2; ++i)
#pragma unroll
            for (int j = 0; j < 4; ++j)
#pragma unroll
                for (int k = 0; k < 4; ++k) acc[i][j][k] = 0.f;

        uint32_t abase_r[2], xa[2];
#pragma unroll
        for (int mi = 0; mi < 2; ++mi) {
            const int arow = wm + mi * 16 + (lane & 15);
            abase_r[mi] = (uint32_t)arow * 64;
            xa[mi] = (arow >> 1) & 3;
        }
        uint32_t bbase_r[2], xb[2];
#pragma unroll
        for (int nb = 0; nb < 2; ++nb) {
            const int brow = wn4 + nb * 16 + (lane & 15);
            bbase_r[nb] = (uint32_t)brow * 64;
            xb[nb] = (brow >> 1) & 3;
        }

        VISSUE(0, 0);
        VISSUE(1, 1);

        for (int s = 0; s < 32; ++s) {
            const int st = s % 3;
            if (s < 31) cp_wait<1>(); else cp_wait<0>();
            __syncthreads();
            if (s + 2 < 32) VISSUE(s + 2, (s + 2) % 3);

            const uint32_t ah = sb + st * 8192;
            const uint32_t bh = sb + 24576 + st * 8192;
#pragma unroll
            for (int kb = 0; kb < 2; ++kb) {
                const uint32_t ccol = kb * 2 + chalf;
                uint32_t a_h[2][4];
#pragma unroll
                for (int mi = 0; mi < 2; ++mi) {
                    const uint32_t aoff = abase_r[mi] + ((ccol ^ xa[mi]) << 4);
                    ldsm4(a_h[mi], ah + aoff);
                }
#pragma unroll
                for (int nb = 0; nb < 2; ++nb) {
                    const uint32_t boff = bbase_r[nb] + ((ccol ^ xb[nb]) << 4);
                    uint32_t bh4[4];
                    ldsm4(bh4, bh + boff);
                    uint32_t b0h[2] = {bh4[0], bh4[2]}, b1h[2] = {bh4[1], bh4[3]};
#pragma unroll
                    for (int mi = 0; mi < 2; ++mi) {
                        mma_hf(acc[mi][nb * 2],     a_h[mi], b0h);
                        mma_hf(acc[mi][nb * 2 + 1], a_h[mi], b1h);
                    }
                }
            }
        }
        __syncthreads();

        uint32_t* Ch = (uint32_t*)smq;
#pragma unroll
        for (int mi = 0; mi < 2; ++mi) {
#pragma unroll
            for (int n8 = 0; n8 < 4; ++n8) {
                const int ncol = wn4 + n8 * 8 + (lane & 3) * 2;
                const float2 bv2 = *(const float2*)(bv + bx * 128 + ncol);
                const int colu = ncol >> 1;
#pragma unroll
                for (int rr = 0; rr < 2; ++rr) {
                    const int row = wm + mi * 16 + (lane >> 2) + rr * 8;
                    const float x0 = acc[mi][n8][rr * 2 + 0] + bv2.x;
                    const float x1 = acc[mi][n8][rr * 2 + 1] + bv2.y;
                    Ch[row * 68 + colu] = phf2(x0, x1);
                }
            }
        }
        __syncthreads();

#pragma unroll
        for (int it = 0; it < 4; ++it) {
            const int idx = tid + it * 512;
            const int j = idx & 7;
            const int row = (idx >> 3) & 127;
            const int half = (idx >> 10) & 1;
            const uint32_t sbyte = (uint32_t)row * 272 + half * 128 + j * 16;
            const uint4 v = *(const uint4*)(smq + sbyte);
            const int m = by * 128 + row;
            const int bsel = m >> 10, sq = m & 1023;
            const int head = bx * 2 + half;
            const size_t off = (((size_t)(bsel * NHt + head)) * St + sq) * HDt + j * 8;
            *(uint4*)(g_vh + off) = v;
        }
#undef VISSUE
    }
}

// ====== Flash attention (R13 config: 64-q CTA, 128 thr, 2-stage KV) ========
#define A_STAGE 27648
#define A_KV0   18432
#define A_MB    73728
#define ASMEM   74240

__global__ __launch_bounds__(128)
void attn_mma(const float* __restrict__ mask, float* __restrict__ out)
{
    extern __shared__ __align__(16) char sma[];
    const uint32_t sb = cvta_s(sma);
    __half (*Qh)[72] = (__half(*)[72])(sma);
    __half (*Ql)[72] = (__half(*)[72])(sma + 9216);

    const int tid = threadIdx.x;
    const int lane = tid & 31, wid = tid >> 5;
    const int qt = blockIdx.x, h = blockIdx.y, b = blockIdx.z;

    const size_t bh = ((size_t)(b * NHt + h)) * St * HDt;
    const __half* qhp = g_qh + bh + (size_t)qt * 64 * HDt;
    const __half* qlp = g_ql + bh + (size_t)qt * 64 * HDt;
    const __half* khp = g_kh + bh;
    const __half* klp = g_kl + bh;
    const __half* vhp = g_vh + bh;
    const float* mrow = mask + (size_t)b * St;

#define AISSUE(ktv, stv) do {                                                 \
        const size_t ko_ = (size_t)(ktv) * 64 * HDt;                          \
        const uint32_t base_ = sb + A_KV0 + (stv) * A_STAGE;                  \
        _Pragma("unroll")                                                     \
        for (int j_ = 0; j_ < 4; ++j_) {                                      \
            const int i_ = tid + j_ * 128;                                    \
            const int r_ = i_ >> 3, c_ = (i_ & 7) * 8;                        \
            const uint32_t d_ = base_ + (uint32_t)r_ * 144 + c_ * 2;          \
            cpa16(d_,         khp + ko_ + r_ * 64 + c_);                      \
            cpa16(d_ + 9216,  klp + ko_ + r_ * 64 + c_);                      \
            cpa16(d_ + 18432, vhp + ko_ + r_ * 64 + c_);                      \
        }                                                                     \
        if (tid < 64) cpa4(sb + A_MB + (stv) * 256 + tid * 4,                 \
                           mrow + (ktv) * 64 + tid);                          \
        cp_commit();                                                          \
    } while (0)

    for (int i = tid; i < 512; i += 128) {
        const int r = i >> 3, c = (i & 7) * 8;
        *(uint4*)&Qh[r][c] = *(const uint4*)(qhp + r * 64 + c);
        *(uint4*)&Ql[r][c] = *(const uint4*)(qlp + r * 64 + c);
    }

    AISSUE(0, 0);

    float o[8][4];
#pragma unroll
    for (int j = 0; j < 8; ++j)
#pragma unroll
        for (int k = 0; k < 4; ++k) o[j][k] = 0.f;
    float m0 = -1e30f, m1 = -1e30f, l0 = 0.f, l1 = 0.f;

    for (int kt = 0; kt < 16; ++kt) {
        const int st = kt & 1;
        cp_wait<0>();
        __syncthreads();
        if (kt + 1 < 16) AISSUE(kt + 1, st ^ 1);

        const uint32_t kh = sb + A_KV0 + st * A_STAGE;
        const uint32_t kl = kh + 9216;
        const uint32_t vs = kh + 18432;
        const float* mbs = (const float*)(sma + A_MB + st * 256);

        float s[8][4];
#pragma unroll
        for (int j = 0; j < 8; ++j)
#pragma unroll
            for (int k = 0; k < 4; ++k) s[j][k] = 0.f;

#pragma unroll
        for (int kb = 0; kb < 4; ++kb) {
            uint32_t aqh[4], aql[4];
            const int qrow = wid * 16 + (lane & 15);
            const int qcol = kb * 16 + (lane >> 4) * 8;
            ldsm4(aqh, cvta_s(&Qh[qrow][qcol]));
            ldsm4(aql, cvta_s(&Ql[qrow][qcol]));
#pragma unroll
            for (int nb = 0; nb < 4; ++nb) {
                const int krow = nb * 16 + (lane & 15);
                const uint32_t koff = (uint32_t)krow * 144 + qcol * 2;
                uint32_t bh4[4], bl4[4];
                ldsm4(bh4, kh + koff);
                ldsm4(bl4, kl + koff);
                uint32_t b0h[2] = {bh4[0], bh4[2]}, b1h[2] = {bh4[1], bh4[3]};
                uint32_t b0l[2] = {bl4[0], bl4[2]}, b1l[2] = {bl4[1], bl4[3]};
                float* s0 = s[nb * 2];
                float* s1 = s[nb * 2 + 1];
                // interleaved: per-accumulator order unchanged (h*h, l*h, h*l)
                mma_hf(s0, aqh, b0h); mma_hf(s1, aqh, b1h);
                mma_hf(s0, aql, b0h); mma_hf(s1, aql, b1h);
                mma_hf(s0, aqh, b0l); mma_hf(s1, aqh, b1l);
            }
        }

        float rmax0 = -1e30f, rmax1 = -1e30f;
#pragma unroll
        for (int j = 0; j < 8; ++j) {
            const float bm0 = (mbs[j * 8 + (lane & 3) * 2]     - 2.0f) * 1.0e6f;
            const float bm1 = (mbs[j * 8 + (lane & 3) * 2 + 1] - 2.0f) * 1.0e6f;
            s[j][0] += bm0; s[j][1] += bm1; s[j][2] += bm0; s[j][3] += bm1;
            rmax0 = fmaxf(rmax0, fmaxf(s[j][0], s[j][1]));
            rmax1 = fmaxf(rmax1, fmaxf(s[j][2], s[j][3]));
        }
        rmax0 = fmaxf(rmax0, __shfl_xor_sync(0xffffffffu, rmax0, 1));
        rmax0 = fmaxf(rmax0, __shfl_xor_sync(0xffffffffu, rmax0, 2));
        rmax1 = fmaxf(rmax1, __shfl_xor_sync(0xffffffffu, rmax1, 1));
        rmax1 = fmaxf(rmax1, __shfl_xor_sync(0xffffffffu, rmax1, 2));
        const float mn0 = fmaxf(m0, rmax0), mn1 = fmaxf(m1, rmax1);
        const float c0 = ex2((m0 - mn0) * LOG2E), c1 = ex2((m1 - mn1) * LOG2E);
        float rs0 = 0.f, rs1 = 0.f;

        uint32_t pa[4][4];
#pragma unroll
        for (int j2 = 0; j2 < 4; ++j2) {
#pragma unroll
            for (int q = 0; q < 2; ++q) {
                const int j = j2 * 2 + q;
                const float p0 = ex2((s[j][0] - mn0) * LOG2E);
                const float p1 = ex2((s[j][1] - mn0) * LOG2E);
                const float p2 = ex2((s[j][2] - mn1) * LOG2E);
                const float p3 = ex2((s[j][3] - mn1) * LOG2E);
                rs0 += p0 + p1; rs1 += p2 + p3;
                pa[j2][q * 2 + 0] = phf2(p0, p1);
                pa[j2][q * 2 + 1] = phf2(p2, p3);
            }
        }

        rs0 += __shfl_xor_sync(0xffffffffu, rs0, 1);
        rs0 += __shfl_xor_sync(0xffffffffu, rs0, 2);
        rs1 += __shfl_xor_sync(0xffffffffu, rs1, 1);
        rs1 += __shfl_xor_sync(0xffffffffu, rs1, 2);
        l0 = l0 * c0 + rs0; l1 = l1 * c1 + rs1;
        m0 = mn0; m1 = mn1;
#pragma unroll
        for (int j = 0; j < 8; ++j) {
            o[j][0] *= c0; o[j][1] *= c0; o[j][2] *= c1; o[j][3] *= c1;
        }

        const int grp = lane >> 3, li = lane & 7;
#pragma unroll
        for (int j2 = 0; j2 < 4; ++j2) {
            const int vr = j2 * 16 + ((grp & 1) ? 8 : 0) + li;
#pragma unroll
            for (int db = 0; db < 4; ++db) {
                const int vc = db * 16 + ((grp >= 2) ? 8 : 0);
                uint32_t vh4[4];
                ldsm4t(vh4, vs + (uint32_t)vr * 144 + vc * 2);
                uint32_t b0h[2] = {vh4[0], vh4[1]}, b1h[2] = {vh4[2], vh4[3]};
                mma_hf(o[db * 2],     pa[j2], b0h);
                mma_hf(o[db * 2 + 1], pa[j2], b1h);
            }
        }
    }

    const float inv0 = 1.f / l0, inv1 = 1.f / l1;
    const int r0 = qt * 64 + wid * 16 + (lane >> 2);
#pragma unroll
    for (int db2 = 0; db2 < 8; ++db2) {
        const int d = db2 * 8 + (lane & 3) * 2;
        float2 v0 = make_float2(o[db2][0] * inv0, o[db2][1] * inv0);
        float2 v1 = make_float2(o[db2][2] * inv1, o[db2][3] * inv1);
        *(float2*)(out + (size_t)(b * St + r0) * HIDt + h * 64 + d) = v0;
        *(float2*)(out + (size_t)(b * St + r0 + 8) * HIDt + h * 64 + d) = v1;
    }
#undef AISSUE
}

extern "C" void kernel_launch(void* const* d_in, const int* in_sizes, int n_in,
                              void* d_out, int out_size)
{
    const float* X    = (const float*)d_in[0];
    const float* mask = (const float*)d_in[1];
    const float* Wq   = (const float*)d_in[2];
    const float* bq   = (const float*)d_in[3];
    const float* Wk   = (const float*)d_in[4];
    const float* bk   = (const float*)d_in[5];
    const float* Wv   = (const float*)d_in[6];
    const float* bv   = (const float*)d_in[7];
    float* out = (float*)d_out;

    cudaFuncSetAttribute(qkv_fused, cudaFuncAttributeMaxDynamicSharedMemorySize, QK2_SMEM);
    cudaFuncSetAttribute(attn_mma, cudaFuncAttributeMaxDynamicSharedMemorySize, ASMEM);

    const int total4 = (XN + 3 * WN) / 4;
    split_prep<<<total4 / 256, 256>>>(X, Wq, Wk, Wv);

    dim3 gqkv(HIDt / 128, (Bt * St) / 128, 2);
    qkv_fused<<<gqkv, 512, QK2_SMEM>>>(bq, bk, bv);

    dim3 g2(St / 64, NHt, Bt);
    attn_mma<<<g2, 128, ASMEM>>>(mask, out);
}

// round 16
// speedup vs baseline: 1.0177x; 1.0045x over previous
#include <cuda_runtime.h>
#include <cuda_fp16.h>
#include <cstdint>

typedef unsigned long long ull;

#define Bt   4
#define St   1024
#define HIDt 1024
#define NHt  16
#define HDt  64
#define LOG2E 1.4426950408889634f
#define NELEM (Bt * NHt * St * HDt)
#define XN (Bt * St * HIDt)
#define WN (HIDt * HIDt)

// fp16 hi/lo split scratch. Q pre-scaled by 0.125. V stored single-fp16.
__device__ __half g_qh[NELEM], g_ql[NELEM];
__device__ __half g_kh[NELEM], g_kl[NELEM];
__device__ __half g_vh[NELEM];
__device__ __half g_xh[XN], g_xl[XN];
__device__ __half g_wh[3 * WN], g_wl[3 * WN];

// ---------------- helpers ----------------
__device__ __forceinline__ uint32_t cvta_s(const void* p) {
    return (uint32_t)__cvta_generic_to_shared(p);
}
__device__ __forceinline__ void ldsm4(uint32_t* r, uint32_t a) {
    asm volatile("ldmatrix.sync.aligned.m8n8.x4.shared.b16 {%0,%1,%2,%3},[%4];"
        : "=r"(r[0]), "=r"(r[1]), "=r"(r[2]), "=r"(r[3]) : "r"(a));
}
__device__ __forceinline__ void ldsm4t(uint32_t* r, uint32_t a) {
    asm volatile("ldmatrix.sync.aligned.m8n8.x4.trans.shared.b16 {%0,%1,%2,%3},[%4];"
        : "=r"(r[0]), "=r"(r[1]), "=r"(r[2]), "=r"(r[3]) : "r"(a));
}
__device__ __forceinline__ void mma_hf(float* c, const uint32_t* a, const uint32_t* b) {
    asm volatile("mma.sync.aligned.m16n8k16.row.col.f32.f16.f16.f32 "
        "{%0,%1,%2,%3},{%4,%5,%6,%7},{%8,%9},{%0,%1,%2,%3};"
        : "+f"(c[0]), "+f"(c[1]), "+f"(c[2]), "+f"(c[3])
        : "r"(a[0]), "r"(a[1]), "r"(a[2]), "r"(a[3]), "r"(b[0]), "r"(b[1]));
}
__device__ __forceinline__ uint32_t phf2(float e0, float e1) {
    uint32_t r; asm("cvt.rn.f16x2.f32 %0, %1, %2;" : "=r"(r) : "f"(e1), "f"(e0)); return r;
}
__device__ __forceinline__ void splith(float x, float& h, float& l) {
    h = __half2float(__float2half(x));
    l = x - h;
}
__device__ __forceinline__ float ex2(float x) {
    float y; asm("ex2.approx.ftz.f32 %0, %1;" : "=f"(y) : "f"(x)); return y;
}
__device__ __forceinline__ void cpa16(uint32_t dst, const void* src) {
    asm volatile("cp.async.cg.shared.global [%0], [%1], 16;" :: "r"(dst), "l"(src));
}
__device__ __forceinline__ void cpa4(uint32_t dst, const void* src) {
    asm volatile("cp.async.ca.shared.global [%0], [%1], 4;" :: "r"(dst), "l"(src));
}
__device__ __forceinline__ void cp_commit() { asm volatile("cp.async.commit_group;"); }
template<int N> __device__ __forceinline__ void cp_wait() {
    asm volatile("cp.async.wait_group %0;" :: "n"(N));
}

// ================= prep: split X / Wq / Wk / Wv to fp16 hi/lo ==============
__global__ __launch_bounds__(256)
void split_prep(const float* __restrict__ X,
                const float* __restrict__ Wq,
                const float* __restrict__ Wk,
                const float* __restrict__ Wv)
{
    const size_t idx = ((size_t)blockIdx.x * 256 + threadIdx.x) * 4;
    const float* src;
    __half *dh, *dl;
    size_t off;
    if (idx < XN)               { src = X;  dh = g_xh; dl = g_xl; off = idx; }
    else if (idx < XN + WN)     { src = Wq; dh = g_wh; dl = g_wl; off = idx - XN; }
    else if (idx < XN + 2 * WN) { src = Wk; dh = g_wh + WN; dl = g_wl + WN; off = idx - XN - WN; }
    else                        { src = Wv; dh = g_wh + 2 * WN; dl = g_wl + 2 * WN; off = idx - XN - 2 * WN; }
    const float4 v = *(const float4*)(src + off);
    float h0, l0, h1, l1, h2, l2, h3, l3;
    splith(v.x, h0, l0); splith(v.y, h1, l1);
    splith(v.z, h2, l2); splith(v.w, h3, l3);
    *(uint2*)(dh + off) = make_uint2(phf2(h0, h1), phf2(h2, h3));
    *(uint2*)(dl + off) = make_uint2(phf2(l0, l1), phf2(l2, l3));
}

// ===== Fused projection kernel: z=0 -> QK (128x256, 3-term), z=1 -> V ======
#define QK_S_AH 0
#define QK_S_AL 24576
#define QK_S_BH 49152
#define QK_S_BL 98304
#define QK2_SMEM 147456

__global__ __launch_bounds__(512, 1)
void qkv_fused(const float* __restrict__ bq, const float* __restrict__ bk,
               const float* __restrict__ bv)
{
    extern __shared__ __align__(16) char smq[];
    const uint32_t sb = cvta_s(smq);

    const int tid = threadIdx.x;
    const int wid = tid >> 5, lane = tid & 31;
    const int bx = blockIdx.x, by = blockIdx.y;
    const int chalf = lane >> 4;

    if (blockIdx.z == 0) {
        const int wm = (wid & 3) * 32;
        const int wn = (wid >> 2) * 64;

        const int rA = tid >> 2, cA = tid & 3;
        const __half* Axh = g_xh + (size_t)(by * 128 + rA) * HIDt;
        const __half* Axl = g_xl + (size_t)(by * 128 + rA) * HIDt;
        const uint32_t swA = (uint32_t)rA * 64 + (((uint32_t)cA ^ ((rA >> 1) & 3)) << 4);

        const int rB = tid >> 1, chp = (tid & 1) * 2;
        const size_t woff = (size_t)(rB >> 7) * WN + (size_t)(bx * 128 + (rB & 127)) * HIDt;
        const __half* Bwh = g_wh + woff;
        const __half* Bwl = g_wl + woff;
        const uint32_t xsB = (rB >> 1) & 3;
        const uint32_t swB0 = (uint32_t)rB * 64 + ((((uint32_t)chp + 0) ^ xsB) << 4);
        const uint32_t swB1 = (uint32_t)rB * 64 + ((((uint32_t)chp + 1) ^ xsB) << 4);

#define QKISSUE(slab, st) do {                                                  \
        const int k0_ = (slab) * 32;                                            \
        cpa16(sb + QK_S_AH + (st) * 8192 + swA, Axh + k0_ + cA * 8);            \
        cpa16(sb + QK_S_AL + (st) * 8192 + swA, Axl + k0_ + cA * 8);            \
        cpa16(sb + QK_S_BH + (st) * 16384 + swB0, Bwh + k0_ + chp * 8);         \
        cpa16(sb + QK_S_BH + (st) * 16384 + swB1, Bwh + k0_ + chp * 8 + 8);     \
        cpa16(sb + QK_S_BL + (st) * 16384 + swB0, Bwl + k0_ + chp * 8);         \
        cpa16(sb + QK_S_BL + (st) * 16384 + swB1, Bwl + k0_ + chp * 8 + 8);     \
        cp_commit();                                                            \
    } while (0)

        float acc[2][8][4];
#pragma unroll
        for (int i = 0; i < 2; ++i)
#pragma unroll
            for (int j = 0; j < 8; ++j)
#pragma unroll
                for (int k = 0; k < 4; ++k) acc[i][j][k] = 0.f;

        uint32_t abase_r[2], xa[2];
#pragma unroll
        for (int mi = 0; mi < 2; ++mi) {
            const int arow = wm + mi * 16 + (lane & 15);
            abase_r[mi] = (uint32_t)arow * 64;
            xa[mi] = (arow >> 1) & 3;
        }
        uint32_t bbase_r[4], xb[4];
#pragma unroll
        for (int nb = 0; nb < 4; ++nb) {
            const int brow = wn + nb * 16 + (lane & 15);
            bbase_r[nb] = (uint32_t)brow * 64;
            xb[nb] = (brow >> 1) & 3;
        }

        QKISSUE(0, 0);
        QKISSUE(1, 1);

        for (int s = 0; s < 32; ++s) {
            const int st = s % 3;
            if (s < 31) cp_wait<1>(); else cp_wait<0>();
            __syncthreads();
            if (s + 2 < 32) QKISSUE(s + 2, (s + 2) % 3);

            const uint32_t ah = sb + QK_S_AH + st * 8192;
            const uint32_t al = sb + QK_S_AL + st * 8192;
            const uint32_t bh = sb + QK_S_BH + st * 16384;
            const uint32_t bl = sb + QK_S_BL + st * 16384;
#pragma unroll
            for (int kb = 0; kb < 2; ++kb) {
                const uint32_t ccol = kb * 2 + chalf;
                uint32_t a_h[2][4], a_l[2][4];
#pragma unroll
                for (int mi = 0; mi < 2; ++mi) {
                    const uint32_t aoff = abase_r[mi] + ((ccol ^ xa[mi]) << 4);
                    ldsm4(a_h[mi], ah + aoff);
                    ldsm4(a_l[mi], al + aoff);
                }
#pragma unroll
                for (int nb = 0; nb < 4; ++nb) {
                    const uint32_t boff = bbase_r[nb] + ((ccol ^ xb[nb]) << 4);
                    uint32_t bh4[4], bl4[4];
                    ldsm4(bh4, bh + boff);
                    ldsm4(bl4, bl + boff);
                    uint32_t b0h[2] = {bh4[0], bh4[2]}, b1h[2] = {bh4[1], bh4[3]};
                    uint32_t b0l[2] = {bl4[0], bl4[2]}, b1l[2] = {bl4[1], bl4[3]};
#pragma unroll
                    for (int mi = 0; mi < 2; ++mi) {
                        float* c0 = acc[mi][nb * 2];
                        float* c1 = acc[mi][nb * 2 + 1];
                        mma_hf(c0, a_h[mi], b0h); mma_hf(c0, a_l[mi], b0h); mma_hf(c0, a_h[mi], b0l);
                        mma_hf(c1, a_h[mi], b1h); mma_hf(c1, a_l[mi], b1h); mma_hf(c1, a_h[mi], b1l);
                    }
                }
            }
        }
        __syncthreads();

        uint32_t* Cp = (uint32_t*)smq;
        const float* bias = (wn < 128) ? bq : bk;
        const float qs = (wn < 128) ? 0.125f : 1.0f;
#pragma unroll
        for (int mi = 0; mi < 2; ++mi) {
#pragma unroll
            for (int nb2 = 0; nb2 < 8; ++nb2) {
                const int ncol = wn + nb2 * 8 + (lane & 3) * 2;
                const float2 bv2 = *(const float2*)(bias + bx * 128 + (ncol & 127));
                const int colu = ncol >> 1;
#pragma unroll
                for (int rr = 0; rr < 2; ++rr) {
                    const int row = wm + mi * 16 + (lane >> 2) + rr * 8;
                    const float x0 = (acc[mi][nb2][rr * 2 + 0] + bv2.x) * qs;
                    const float x1 = (acc[mi][nb2][rr * 2 + 1] + bv2.y) * qs;
                    float h0, l0, h1, l1;
                    splith(x0, h0, l0); splith(x1, h1, l1);
                    Cp[row * 132 + colu]         = phf2(h0, h1);
                    Cp[16896 + row * 132 + colu] = phf2(l0, l1);
                }
            }
        }
        __syncthreads();

#pragma unroll
        for (int it = 0; it < 16; ++it) {
            const int idx = tid + it * 512;
            const int a = idx >> 12;
            const int rem = idx & 4095;
            const int row = rem >> 5;
            const int j = rem & 31;
            const uint32_t sbyte = (uint32_t)a * 67584 + (uint32_t)row * 528 + j * 16;
            const uint4 v = *(const uint4*)(smq + sbyte);
            const int n = j * 8;
            const int ncol = n & 127;
            __half* dst = (n < 128) ? (a ? g_ql : g_qh) : (a ? g_kl : g_kh);
            const int m = by * 128 + row;
            const int bsel = m >> 10, sq = m & 1023;
            const int head = bx * 2 + (ncol >> 6);
            const size_t off = (((size_t)(bsel * NHt + head)) * St + sq) * HDt + (ncol & 63);
            *(uint4*)(dst + off) = v;
        }
#undef QKISSUE
    } else {
        // ---------------- V path: 128x128, 1-term, 512 threads, 4x4 warps --
        const int wm = (wid & 3) * 32;
        const int wn4 = (wid >> 2) * 32;

        const int rA = tid >> 2, cA = tid & 3;
        const __half* Axh = g_xh + (size_t)(by * 128 + rA) * HIDt + cA * 8;
        const __half* Bwh = g_wh + 2 * (size_t)WN + (size_t)(bx * 128 + rA) * HIDt + cA * 8;
        const uint32_t swA = (uint32_t)rA * 64 + (((uint32_t)cA ^ ((rA >> 1) & 3)) << 4);

#define VISSUE(slab, st) do {                                            \
        const int k0_ = (slab) * 32;                                     \
        cpa16(sb + (st) * 8192 + swA, Axh + k0_);                        \
        cpa16(sb + 24576 + (st) * 8192 + swA, Bwh + k0_);                \
        cp_commit();                                                     \
    } while (0)

        float acc[2][4][4];
#pragma unroll
        for (int i = 0; i < 2; ++i)
#pragma unroll
            for (int j = 0; j < 4; ++j)
#pragma unroll
                for (int k = 0; k < 4; ++k) acc[i][j][k] = 0.f;

        uint32_t abase_r[2], xa[2];
#pragma unroll
        for (int mi = 0; mi < 2; ++mi) {
            const int arow = wm + mi * 16 + (lane & 15);
            abase_r[mi] = (uint32_t)arow * 64;
            xa[mi] = (arow >> 1) & 3;
        }
        uint32_t bbase_r[2], xb[2];
#pragma unroll
        for (int nb = 0; nb < 2; ++nb) {
            const int brow = wn4 + nb * 16 + (lane & 15);
            bbase_r[nb] = (uint32_t)brow * 64;
            xb[nb] = (brow >> 1) & 3;
        }

        VISSUE(0, 0);
        VISSUE(1, 1);

        for (int s = 0; s < 32; ++s) {
            const int st = s % 3;
            if (s < 31) cp_wait<1>(); else cp_wait<0>();
            __syncthreads();
            if (s + 2 < 32) VISSUE(s + 2, (s + 2) % 3);

            const uint32_t ah = sb + st * 8192;
            const uint32_t bh = sb + 24576 + st * 8192;
#pragma unroll
            for (int kb = 0; kb < 2; ++kb) {
                const uint32_t ccol = kb * 2 + chalf;
                uint32_t a_h[2][4];
#pragma unroll
                for (int mi = 0; mi < 2; ++mi) {
                    const uint32_t aoff = abase_r[mi] + ((ccol ^ xa[mi]) << 4);
                    ldsm4(a_h[mi], ah + aoff);
                }
#pragma unroll
                for (int nb = 0; nb < 2; ++nb) {
                    const uint32_t boff = bbase_r[nb] + ((ccol ^ xb[nb]) << 4);
                    uint32_t bh4[4];
                    ldsm4(bh4, bh + boff);
                    uint32_t b0h[2] = {bh4[0], bh4[2]}, b1h[2] = {bh4[1], bh4[3]};
#pragma unroll
                    for (int mi = 0; mi < 2; ++mi) {
                        mma_hf(acc[mi][nb * 2],     a_h[mi], b0h);
                        mma_hf(acc[mi][nb * 2 + 1], a_h[mi], b1h);
                    }
                }
            }
        }
        __syncthreads();

        uint32_t* Ch = (uint32_t*)smq;
#pragma unroll
        for (int mi = 0; mi < 2; ++mi) {
#pragma unroll
            for (int n8 = 0; n8 < 4; ++n8) {
                const int ncol = wn4 + n8 * 8 + (lane & 3) * 2;
                const float2 bv2 = *(const float2*)(bv + bx * 128 + ncol);
                const int colu = ncol >> 1;
#pragma unroll
                for (int rr = 0; rr < 2; ++rr) {
                    const int row = wm + mi * 16 + (lane >> 2) + rr * 8;
                    const float x0 = acc[mi][n8][rr * 2 + 0] + bv2.x;
                    const float x1 = acc[mi][n8][rr * 2 + 1] + bv2.y;
                    Ch[row * 68 + colu] = phf2(x0, x1);
                }
            }
        }
        __syncthreads();

#pragma unroll
        for (int it = 0; it < 4; ++it) {
            const int idx = tid + it * 512;
            const int j = idx & 7;
            const int row = (idx >> 3) & 127;
            const int half = (idx >> 10) & 1;
            const uint32_t sbyte = (uint32_t)row * 272 + half * 128 + j * 16;
            const uint4 v = *(const uint4*)(smq + sbyte);
            const int m = by * 128 + row;
            const int bsel = m >> 10, sq = m & 1023;
            const int head = bx * 2 + half;
            const size_t off = (((size_t)(bsel * NHt + head)) * St + sq) * HDt + j * 8;
            *(uint4*)(g_vh + off) = v;
        }
#undef VISSUE
    }
}

// == Flash attention: 64-q CTA, 128 thr, 2-stage KV, Q frags direct from gmem
// smem: stage st at st*27648 (Kh +0, Kl +9216, Vs +18432); mask at 55296.
#define A_STAGE 27648
#define A_MB    55296
#define ASMEM   55808

__global__ __launch_bounds__(128, 4)
void attn_mma(const float* __restrict__ mask, float* __restrict__ out)
{
    extern __shared__ __align__(16) char sma[];
    const uint32_t sb = cvta_s(sma);

    const int tid = threadIdx.x;
    const int lane = tid & 31, wid = tid >> 5;
    const int qt = blockIdx.x, h = blockIdx.y, b = blockIdx.z;

    const size_t bh = ((size_t)(b * NHt + h)) * St * HDt;
    const __half* qhp = g_qh + bh + (size_t)qt * 64 * HDt;
    const __half* qlp = g_ql + bh + (size_t)qt * 64 * HDt;
    const __half* khp = g_kh + bh;
    const __half* klp = g_kl + bh;
    const __half* vhp = g_vh + bh;
    const float* mrow = mask + (size_t)b * St;

#define AISSUE(ktv, stv) do {                                                 \
        const size_t ko_ = (size_t)(ktv) * 64 * HDt;                          \
        const uint32_t base_ = sb + (stv) * A_STAGE;                          \
        _Pragma("unroll")                                                     \
        for (int j_ = 0; j_ < 4; ++j_) {                                      \
            const int i_ = tid + j_ * 128;                                    \
            const int r_ = i_ >> 3, c_ = (i_ & 7) * 8;                        \
            const uint32_t d_ = base_ + (uint32_t)r_ * 144 + c_ * 2;          \
            cpa16(d_,         khp + ko_ + r_ * 64 + c_);                      \
            cpa16(d_ + 9216,  klp + ko_ + r_ * 64 + c_);                      \
            cpa16(d_ + 18432, vhp + ko_ + r_ * 64 + c_);                      \
        }                                                                     \
        if (tid < 64) cpa4(sb + A_MB + (stv) * 256 + tid * 4,                 \
                           mrow + (ktv) * 64 + tid);                          \
        cp_commit();                                                          \
    } while (0)

    AISSUE(0, 0);

    // Q fragments loaded directly from gmem (mma A-frag layout), once.
    uint32_t qf_h[4][4], qf_l[4][4];
    {
        const int r0q = wid * 16 + (lane >> 2);           // rows r0q, r0q+8
        const int c0q = (lane & 3) * 2;
#pragma unroll
        for (int kb = 0; kb < 4; ++kb) {
            const int k0 = kb * 16 + c0q;
            qf_h[kb][0] = *(const uint32_t*)(qhp + (size_t)r0q * 64 + k0);
            qf_h[kb][1] = *(const uint32_t*)(qhp + (size_t)(r0q + 8) * 64 + k0);
            qf_h[kb][2] = *(const uint32_t*)(qhp + (size_t)r0q * 64 + k0 + 8);
            qf_h[kb][3] = *(const uint32_t*)(qhp + (size_t)(r0q + 8) * 64 + k0 + 8);
            qf_l[kb][0] = *(const uint32_t*)(qlp + (size_t)r0q * 64 + k0);
            qf_l[kb][1] = *(const uint32_t*)(qlp + (size_t)(r0q + 8) * 64 + k0);
            qf_l[kb][2] = *(const uint32_t*)(qlp + (size_t)r0q * 64 + k0 + 8);
            qf_l[kb][3] = *(const uint32_t*)(qlp + (size_t)(r0q + 8) * 64 + k0 + 8);
        }
    }

    float o[8][4];
#pragma unroll
    for (int j = 0; j < 8; ++j)
#pragma unroll
        for (int k = 0; k < 4; ++k) o[j][k] = 0.f;
    float m0 = -1e30f, m1 = -1e30f, l0 = 0.f, l1 = 0.f;

    for (int kt = 0; kt < 16; ++kt) {
        const int st = kt & 1;
        cp_wait<0>();
        __syncthreads();
        if (kt + 1 < 16) AISSUE(kt + 1, st ^ 1);

        const uint32_t kh = sb + st * A_STAGE;
        const uint32_t kl = kh + 9216;
        const uint32_t vs = kh + 18432;
        const float* mbs = (const float*)(sma + A_MB + st * 256);

        float s[8][4];
#pragma unroll
        for (int j = 0; j < 8; ++j)
#pragma unroll
            for (int k = 0; k < 4; ++k) s[j][k] = 0.f;

#pragma unroll
        for (int kb = 0; kb < 4; ++kb) {
            const int qcol = kb * 16 + (lane >> 4) * 8;
#pragma unroll
            for (int nb = 0; nb < 4; ++nb) {
                const int krow = nb * 16 + (lane & 15);
                const uint32_t koff = (uint32_t)krow * 144 + qcol * 2;
                uint32_t bh4[4], bl4[4];
                ldsm4(bh4, kh + koff);
                ldsm4(bl4, kl + koff);
                uint32_t b0h[2] = {bh4[0], bh4[2]}, b1h[2] = {bh4[1], bh4[3]};
                uint32_t b0l[2] = {bl4[0], bl4[2]}, b1l[2] = {bl4[1], bl4[3]};
                float* s0 = s[nb * 2];
                float* s1 = s[nb * 2 + 1];
                mma_hf(s0, qf_h[kb], b0h); mma_hf(s0, qf_l[kb], b0h); mma_hf(s0, qf_h[kb], b0l);
                mma_hf(s1, qf_h[kb], b1h); mma_hf(s1, qf_l[kb], b1h); mma_hf(s1, qf_h[kb], b1l);
            }
        }

        float rmax0 = -1e30f, rmax1 = -1e30f;
#pragma unroll
        for (int j = 0; j < 8; ++j) {
            const float bm0 = (mbs[j * 8 + (lane & 3) * 2]     - 2.0f) * 1.0e6f;
            const float bm1 = (mbs[j * 8 + (lane & 3) * 2 + 1] - 2.0f) * 1.0e6f;
            s[j][0] += bm0; s[j][1] += bm1; s[j][2] += bm0; s[j][3] += bm1;
            rmax0 = fmaxf(rmax0, fmaxf(s[j][0], s[j][1]));
            rmax1 = fmaxf(rmax1, fmaxf(s[j][2], s[j][3]));
        }
        rmax0 = fmaxf(rmax0, __shfl_xor_sync(0xffffffffu, rmax0, 1));
        rmax0 = fmaxf(rmax0, __shfl_xor_sync(0xffffffffu, rmax0, 2));
        rmax1 = fmaxf(rmax1, __shfl_xor_sync(0xffffffffu, rmax1, 1));
        rmax1 = fmaxf(rmax1, __shfl_xor_sync(0xffffffffu, rmax1, 2));
        const float mn0 = fmaxf(m0, rmax0), mn1 = fmaxf(m1, rmax1);
        const float c0 = ex2((m0 - mn0) * LOG2E), c1 = ex2((m1 - mn1) * LOG2E);
        float rs0 = 0.f, rs1 = 0.f;

        uint32_t pa[4][4];
#pragma unroll
        for (int j2 = 0; j2 < 4; ++j2) {
#pragma unroll
            for (int q = 0; q < 2; ++q) {
                const int j = j2 * 2 + q;
                const float p0 = ex2((s[j][0] - mn0) * LOG2E);
                const float p1 = ex2((s[j][1] - mn0) * LOG2E);
                const float p2 = ex2((s[j][2] - mn1) * LOG2E);
                const float p3 = ex2((s[j][3] - mn1) * LOG2E);
                rs0 += p0 + p1; rs1 += p2 + p3;
                pa[j2][q * 2 + 0] = phf2(p0, p1);
                pa[j2][q * 2 + 1] = phf2(p2, p3);
            }
        }

        rs0 += __shfl_xor_sync(0xffffffffu, rs0, 1);
        rs0 += __shfl_xor_sync(0xffffffffu, rs0, 2);
        rs1 += __shfl_xor_sync(0xffffffffu, rs1, 1);
        rs1 += __shfl_xor_sync(0xffffffffu, rs1, 2);
        l0 = l0 * c0 + rs0; l1 = l1 * c1 + rs1;
        m0 = mn0; m1 = mn1;
#pragma unroll
        for (int j = 0; j < 8; ++j) {
            o[j][0] *= c0; o[j][1] *= c0; o[j][2] *= c1; o[j][3] *= c1;
        }

        const int grp = lane >> 3, li = lane & 7;
#pragma unroll
        for (int j2 = 0; j2 < 4; ++j2) {
            const int vr = j2 * 16 + ((grp & 1) ? 8 : 0) + li;
#pragma unroll
            for (int db = 0; db < 4; ++db) {
                const int vc = db * 16 + ((grp >= 2) ? 8 : 0);
                uint32_t vh4[4];
                ldsm4t(vh4, vs + (uint32_t)vr * 144 + vc * 2);
                uint32_t b0h[2] = {vh4[0], vh4[1]}, b1h[2] = {vh4[2], vh4[3]};
                mma_hf(o[db * 2],     pa[j2], b0h);
                mma_hf(o[db * 2 + 1], pa[j2], b1h);
            }
        }
    }

    const float inv0 = 1.f / l0, inv1 = 1.f / l1;
    const int r0 = qt * 64 + wid * 16 + (lane >> 2);
#pragma unroll
    for (int db2 = 0; db2 < 8; ++db2) {
        const int d = db2 * 8 + (lane & 3) * 2;
        float2 v0 = make_float2(o[db2][0] * inv0, o[db2][1] * inv0);
        float2 v1 = make_float2(o[db2][2] * inv1, o[db2][3] * inv1);
        *(float2*)(out + (size_t)(b * St + r0) * HIDt + h * 64 + d) = v0;
        *(float2*)(out + (size_t)(b * St + r0 + 8) * HIDt + h * 64 + d) = v1;
    }
#undef AISSUE
}

extern "C" void kernel_launch(void* const* d_in, const int* in_sizes, int n_in,
                              void* d_out, int out_size)
{
    const float* X    = (const float*)d_in[0];
    const float* mask = (const float*)d_in[1];
    const float* Wq   = (const float*)d_in[2];
    const float* bq   = (const float*)d_in[3];
    const float* Wk   = (const float*)d_in[4];
    const float* bk   = (const float*)d_in[5];
    const float* Wv   = (const float*)d_in[6];
    const float* bv   = (const float*)d_in[7];
    float* out = (float*)d_out;

    cudaFuncSetAttribute(qkv_fused, cudaFuncAttributeMaxDynamicSharedMemorySize, QK2_SMEM);
    cudaFuncSetAttribute(attn_mma, cudaFuncAttributeMaxDynamicSharedMemorySize, ASMEM);

    const int total4 = (XN + 3 * WN) / 4;
    split_prep<<<total4 / 256, 256>>>(X, Wq, Wk, Wv);

    dim3 gqkv(HIDt / 128, (Bt * St) / 128, 2);
    qkv_fused<<<gqkv, 512, QK2_SMEM>>>(bq, bk, bv);

    dim3 g2(St / 64, NHt, Bt);
    attn_mma<<<g2, 128, ASMEM>>>(mask, out);
}